// round 10
// baseline (speedup 1.0000x reference)
#include <cuda_runtime.h>
#include <cstdio>
#include <cstdint>

#define B_   8
#define NQ_  75
#define NS_  5
#define NG_  4
#define NF_  49
#define C_   64

#define ROWS_ 294
#define STR_  68
#define NT2_  320

__device__ float g_p1[B_ * NQ_ * NS_ * NG_];
__device__ float g_p2[B_ * NQ_ * NS_ * NG_];

__device__ __forceinline__ float multi_gauss(float d2) {
    d2 = fmaxf(d2, 0.0f);
    float t  = __expf(-0.125f * d2);
    float t2 = t * t;
    float t4 = t2 * t2;
    float t8 = t4 * t4;
    float t16 = t8 * t8;
    return t + t2 + t4 + t8 + t16;
}

// ---------------------------------------------------------------------------
// k1: fused Kss + bilinear. Grid 800 = (b, vchunk of 15, s, g).
// Phase 1: 289 threads compute Kss(49x49) via 3x3 micro-tiles -> smem.
// Phase 2: 320 threads compute beta^T Kss beta for 15 queries -> g_p1.
// ---------------------------------------------------------------------------
__global__ __launch_bounds__(320) void k1_fused(const float* __restrict__ sup,
                                                const float* __restrict__ beta) {
    __shared__ float xs[51 * STR_];
    __shared__ float ssq[52];
    __shared__ float kss[49 * 50];
    __shared__ float betas[15 * 50];
    __shared__ float scr[736];

    int bid = blockIdx.x;              // 0..799
    int g = bid & 3;
    int rest = bid >> 2;
    int s = rest % NS_;  rest /= NS_;
    int vt = rest % 5;
    int b = rest / 5;
    int tid = threadIdx.x;

    const float* sb = sup + (size_t)(((b * NS_ + s) * NG_ + g)) * 49 * 64;
    // load support tile (rows 49,50 zero-padded for the 3x3 tiling)
    for (int idx = tid; idx < 51 * 16; idx += 320) {
        int r = idx >> 4, c4 = idx & 15;
        float4 v = make_float4(0.f, 0.f, 0.f, 0.f);
        if (r < 49) v = *(const float4*)(sb + r * 64 + c4 * 4);
        *(float4*)(xs + r * STR_ + c4 * 4) = v;
    }
    for (int idx = tid; idx < 15 * 49; idx += 320) {
        int vv = idx / 49, j = idx - vv * 49;
        int v = vt * 15 + vv;
        size_t off = ((size_t)((b * NQ_ + v) * NS_ + s) * NG_ + g) * 49 + j;
        betas[vv * 50 + j] = beta[off];
    }
    __syncthreads();

    if (tid < 51) {
        const float2* xr = (const float2*)(xs + tid * STR_);
        float a0 = 0.f, a1 = 0.f;
        #pragma unroll
        for (int c = 0; c < 32; c++) { float2 x = xr[c]; a0 = fmaf(x.x, x.x, a0); a1 = fmaf(x.y, x.y, a1); }
        ssq[tid] = a0 + a1;
    }
    __syncthreads();

    // Phase 1: 17x17 grid of 3x3 micro-tiles
    if (tid < 289) {
        int it = tid / 17, jt = tid - it * 17;
        float acc[9];
        #pragma unroll
        for (int k = 0; k < 9; k++) acc[k] = 0.f;
        const float2* A  = (const float2*)(xs + it * 3 * STR_);
        const float2* Bm = (const float2*)(xs + jt * 3 * STR_);
        #pragma unroll 2
        for (int c2 = 0; c2 < 32; c2++) {
            float2 a[3], bb[3];
            #pragma unroll
            for (int k = 0; k < 3; k++) a[k]  = A[k * (STR_ / 2) + c2];
            #pragma unroll
            for (int k = 0; k < 3; k++) bb[k] = Bm[k * (STR_ / 2) + c2];
            #pragma unroll
            for (int ii = 0; ii < 3; ii++)
                #pragma unroll
                for (int jj = 0; jj < 3; jj++) {
                    acc[ii * 3 + jj] = fmaf(a[ii].x, bb[jj].x, acc[ii * 3 + jj]);
                    acc[ii * 3 + jj] = fmaf(a[ii].y, bb[jj].y, acc[ii * 3 + jj]);
                }
        }
        #pragma unroll
        for (int ii = 0; ii < 3; ii++) {
            int i = it * 3 + ii;
            #pragma unroll
            for (int jj = 0; jj < 3; jj++) {
                int j = jt * 3 + jj;
                if (i < 49 && j < 49) {
                    float d2 = ssq[i] + ssq[j] - 2.0f * acc[ii * 3 + jj];
                    kss[i * 50 + j] = multi_gauss(d2);
                }
            }
        }
    }
    __syncthreads();

    // Phase 2: bilinear, 735 tasks (15 v x 49 rows)
    for (int t = tid; t < 735; t += 320) {
        int vv = t / 49, i = t - vv * 49;
        const float2* kr = (const float2*)(kss + i * 50);
        const float2* bv = (const float2*)(betas + vv * 50);
        float r0 = 0.f, r1 = 0.f;
        #pragma unroll
        for (int c = 0; c < 24; c++) {
            float2 kk = kr[c], bb = bv[c];
            r0 = fmaf(kk.x, bb.x, r0);
            r1 = fmaf(kk.y, bb.y, r1);
        }
        float r = r0 + r1 + kss[i * 50 + 48] * betas[vv * 50 + 48];
        scr[t] = betas[vv * 50 + i] * r;
    }
    __syncthreads();

    if (tid < 15) {
        float acc = 0.f;
        #pragma unroll
        for (int k = 0; k < 49; k++) acc += scr[tid * 49 + k];
        int v = vt * 15 + tid;
        g_p1[((b * NQ_ + v) * NS_ + s) * NG_ + g] = acc;
    }
}

// ---------------------------------------------------------------------------
// k2: per (b,v,g). R4-exact: batched float4 load (high MLP), separate rsq
// pass, 7x7 scalar-FFMA micro-tiles, fused epilogue, scratch reduce.
// ---------------------------------------------------------------------------
__global__ __launch_bounds__(NT2_, 2) void k2_main(const float* __restrict__ sup,
                                                   const float* __restrict__ qry,
                                                   const float* __restrict__ beta,
                                                   const float* __restrict__ gamma) {
    extern __shared__ float sm[];
    float* xs   = sm;                     // 294*68
    float* rsq  = xs + ROWS_ * STR_;      // 296
    float* bet  = rsq + 296;              // 245
    float* gam  = bet + 245;              // 245
    float* scr  = gam + 245;              // 245
    float* scrq = scr + 245;              // 245
    float* red  = scrq + 245;             // 16

    int bid = blockIdx.x;
    int g = bid & 3;
    int bv = bid >> 2;
    int b = bv / NQ_;
    int tid = threadIdx.x;

    const float* supb = sup + (size_t)(b * (NS_ * NG_) + g) * 49 * 64;
    const float* qryb = qry + ((size_t)bv * NG_ + g) * 49 * 64;

    for (int idx = tid; idx < ROWS_ * 16; idx += NT2_) {
        int r = idx >> 4, c4 = idx & 15;
        float4 val;
        if (r < 245) {
            int s = r / 49;
            int i = r - s * 49;
            val = *(const float4*)(supb + (size_t)s * (NG_ * 49 * 64) + i * 64 + c4 * 4);
        } else {
            val = *(const float4*)(qryb + (r - 245) * 64 + c4 * 4);
        }
        *(float4*)(xs + r * STR_ + c4 * 4) = val;
    }
    for (int idx = tid; idx < NS_ * 49; idx += NT2_) {
        int s = idx / 49, j = idx - s * 49;
        size_t off = ((size_t)(bv * NS_ + s) * NG_ + g) * 49 + j;
        bet[idx] = beta[off];
        gam[idx] = gamma[off];
    }
    __syncthreads();

    for (int r = tid; r < ROWS_; r += NT2_) {
        const float2* xr = (const float2*)(xs + r * STR_);
        float a0 = 0.f, a1 = 0.f;
        #pragma unroll
        for (int c = 0; c < 32; c++) { float2 x = xr[c]; a0 = fmaf(x.x, x.x, a0); a1 = fmaf(x.y, x.y, a1); }
        rsq[r] = a0 + a1;
    }
    __syncthreads();

    bool active = (tid < ROWS_);
    int it = tid / 7;
    int jt = tid - it * 7;

    if (active) {
        float acc[49];
        #pragma unroll
        for (int k = 0; k < 49; k++) acc[k] = 0.0f;

        const float2* A  = (const float2*)(xs + it * 7 * STR_);
        const float2* Bm = (const float2*)(xs + (245 + jt * 7) * STR_);
        #pragma unroll 1
        for (int c2 = 0; c2 < 32; c2++) {
            float2 a[7], bb[7];
            #pragma unroll
            for (int k = 0; k < 7; k++) a[k]  = A[k * (STR_ / 2) + c2];
            #pragma unroll
            for (int k = 0; k < 7; k++) bb[k] = Bm[k * (STR_ / 2) + c2];
            #pragma unroll
            for (int ii = 0; ii < 7; ii++)
                #pragma unroll
                for (int jj = 0; jj < 7; jj++) {
                    acc[ii * 7 + jj] = fmaf(a[ii].x, bb[jj].x, acc[ii * 7 + jj]);
                    acc[ii * 7 + jj] = fmaf(a[ii].y, bb[jj].y, acc[ii * 7 + jj]);
                }
        }

        float qsq[7];
        int jbase = jt * 7;
        #pragma unroll
        for (int jj = 0; jj < 7; jj++) qsq[jj] = rsq[245 + jbase + jj];
        #pragma unroll
        for (int ii = 0; ii < 7; ii++) {
            float ri = rsq[it * 7 + ii];
            #pragma unroll
            for (int jj = 0; jj < 7; jj++) {
                float d2 = ri + qsq[jj] - 2.0f * acc[ii * 7 + jj];
                acc[ii * 7 + jj] = multi_gauss(d2);
            }
        }

        if (it < 35) {
            int s = it / 7;
            int i0 = it * 7 - s * 49;
            const float* gs = gam + s * 49 + jbase;
            const float* bs = bet + s * 49 + i0;
            float partial = 0.0f;
            #pragma unroll
            for (int ii = 0; ii < 7; ii++) {
                float rowsum = 0.0f;
                #pragma unroll
                for (int jj = 0; jj < 7; jj++) rowsum = fmaf(acc[ii * 7 + jj], gs[jj], rowsum);
                partial = fmaf(bs[ii], rowsum, partial);
            }
            scr[tid] = partial;
        } else {
            int q0 = it * 7 - 245;
            int qt = tid - 245;
            #pragma unroll
            for (int s = 0; s < 5; s++) {
                const float* gs = gam + s * 49;
                float pq = 0.0f;
                #pragma unroll
                for (int ii = 0; ii < 7; ii++) {
                    float rowsum = 0.0f;
                    #pragma unroll
                    for (int jj = 0; jj < 7; jj++) rowsum = fmaf(acc[ii * 7 + jj], gs[jbase + jj], rowsum);
                    pq = fmaf(gs[q0 + ii], rowsum, pq);
                }
                scrq[s * 49 + qt] = pq;
            }
        }
    }
    __syncthreads();

    if (tid < 10) {
        int s = tid % 5;
        const float* src = (tid < 5) ? (scr + s * 49) : (scrq + s * 49);
        float acc2 = 0.f;
        #pragma unroll
        for (int k = 0; k < 49; k++) acc2 += src[k];
        red[tid] = acc2;
    }
    __syncthreads();

    if (tid < NS_) {
        int idx = (bv * NS_ + tid) * NG_ + g;
        g_p2[idx] = red[5 + tid] - 2.0f * red[tid];
    }
}

__global__ void k3_reduce(float* __restrict__ out) {
    int o = blockIdx.x * blockDim.x + threadIdx.x;
    if (o < B_ * NQ_ * NS_) {
        float s = 0.0f;
        #pragma unroll
        for (int g = 0; g < NG_; g++) s += g_p1[o * NG_ + g] + g_p2[o * NG_ + g];
        out[o] = 0.25f * s;
    }
}

extern "C" void kernel_launch(void* const* d_in, const int* in_sizes, int n_in,
                              void* d_out, int out_size) {
    const float* sup   = (const float*)d_in[0];
    const float* qry   = (const float*)d_in[1];
    const float* beta  = (const float*)d_in[2];
    const float* gamma = (const float*)d_in[3];
    float* out = (float*)d_out;

    const int smem2 = (ROWS_ * STR_ + 296 + 245 * 4 + 16) * (int)sizeof(float);
    static bool configured = false;
    if (!configured) {
        cudaFuncSetAttribute(k2_main, cudaFuncAttributeMaxDynamicSharedMemorySize, smem2);
        configured = true;
    }

    k1_fused<<<B_ * NS_ * NG_ * 5, 320>>>(sup, beta);
    k2_main<<<B_ * NQ_ * NG_, NT2_, smem2>>>(sup, qry, beta, gamma);
    k3_reduce<<<(B_ * NQ_ * NS_ + 255) / 256, 256>>>(out);
}

// round 11
// speedup vs baseline: 1.0346x; 1.0346x over previous
#include <cuda_runtime.h>
#include <cstdio>
#include <cstdint>

#define B_   8
#define NQ_  75
#define NS_  5
#define NG_  4
#define NF_  49
#define C_   64

#define ROWS_ 294
#define STR_  68
#define NT2_  320

__device__ float g_p1[B_ * NQ_ * NS_ * NG_];
__device__ float g_p2[B_ * NQ_ * NS_ * NG_];
__device__ float g_kss[B_ * NS_ * NG_ * NF_ * NF_];

__device__ __forceinline__ float multi_gauss(float d2) {
    d2 = fmaxf(d2, 0.0f);
    float t  = __expf(-0.125f * d2);
    float t2 = t * t;
    float t4 = t2 * t2;
    float t8 = t4 * t4;
    float t16 = t8 * t8;
    return t + t2 + t4 + t8 + t16;
}

// ---------------------------------------------------------------------------
// k1a: per (b,s,g) -> Kss (49x49) once -> g_kss.
// 169 threads, 13x13 grid of 4x4 micro-tiles (rows padded to 52).
// Per-thread FFMA path ~1k instrs (vs 3.1k at 7x7/49thr); LDS 2 B/FMA, no
// recompute -> neither crossbar- nor latency-bound.
// ---------------------------------------------------------------------------
__global__ __launch_bounds__(192) void k1a_kss(const float* __restrict__ sup) {
    __shared__ float xs[52 * STR_];
    __shared__ float ssq[52];

    int bid = blockIdx.x;              // 0..159 = (b*5+s)*4+g
    int tid = threadIdx.x;

    const float* sb = sup + (size_t)bid * 49 * 64;
    for (int idx = tid; idx < 52 * 16; idx += 192) {
        int r = idx >> 4, c4 = idx & 15;
        float4 v = make_float4(0.f, 0.f, 0.f, 0.f);
        if (r < 49) v = *(const float4*)(sb + r * 64 + c4 * 4);
        *(float4*)(xs + r * STR_ + c4 * 4) = v;
    }
    __syncthreads();

    if (tid < 52) {
        const float2* xr = (const float2*)(xs + tid * STR_);
        float a0 = 0.f, a1 = 0.f;
        #pragma unroll
        for (int c = 0; c < 32; c++) { float2 x = xr[c]; a0 = fmaf(x.x, x.x, a0); a1 = fmaf(x.y, x.y, a1); }
        ssq[tid] = a0 + a1;
    }
    __syncthreads();

    if (tid < 169) {
        int it = tid / 13, jt = tid - it * 13;
        float acc[16];
        #pragma unroll
        for (int k = 0; k < 16; k++) acc[k] = 0.f;
        const float2* A  = (const float2*)(xs + it * 4 * STR_);
        const float2* Bm = (const float2*)(xs + jt * 4 * STR_);
        #pragma unroll 2
        for (int c2 = 0; c2 < 32; c2++) {
            float2 a[4], bb[4];
            #pragma unroll
            for (int k = 0; k < 4; k++) a[k]  = A[k * (STR_ / 2) + c2];
            #pragma unroll
            for (int k = 0; k < 4; k++) bb[k] = Bm[k * (STR_ / 2) + c2];
            #pragma unroll
            for (int ii = 0; ii < 4; ii++)
                #pragma unroll
                for (int jj = 0; jj < 4; jj++) {
                    acc[ii * 4 + jj] = fmaf(a[ii].x, bb[jj].x, acc[ii * 4 + jj]);
                    acc[ii * 4 + jj] = fmaf(a[ii].y, bb[jj].y, acc[ii * 4 + jj]);
                }
        }
        float* kout = g_kss + (size_t)bid * 2401;
        #pragma unroll
        for (int ii = 0; ii < 4; ii++) {
            int i = it * 4 + ii;
            if (i < 49) {
                float ri = ssq[i];
                #pragma unroll
                for (int jj = 0; jj < 4; jj++) {
                    int j = jt * 4 + jj;
                    if (j < 49) {
                        float d2 = ri + ssq[j] - 2.0f * acc[ii * 4 + jj];
                        kout[i * 49 + j] = multi_gauss(d2);
                    }
                }
            }
        }
    }
}

// ---------------------------------------------------------------------------
// k1b: per (b,s,g,vchunk of 15) -> beta^T Kss beta (Kss L2-hot)
// ---------------------------------------------------------------------------
__global__ __launch_bounds__(256) void k1b_bilinear(const float* __restrict__ beta) {
    __shared__ float kss[49 * 50];
    __shared__ float betas[15 * 50];
    __shared__ float scr[735];

    int bid = blockIdx.x;
    int g = bid & 3;
    int rest = bid >> 2;
    int s = rest % NS_;  rest /= NS_;
    int vt = rest % 5;
    int b = rest / 5;
    int tid = threadIdx.x;

    int bid160 = (b * NS_ + s) * NG_ + g;
    const float* ksrc = g_kss + (size_t)bid160 * 2401;
    for (int idx = tid; idx < 2401; idx += 256) {
        int i = idx / 49, j = idx - i * 49;
        kss[i * 50 + j] = ksrc[idx];
    }
    for (int idx = tid; idx < 15 * 49; idx += 256) {
        int vv = idx / 49, j = idx - vv * 49;
        int v = vt * 15 + vv;
        size_t off = ((size_t)((b * NQ_ + v) * NS_ + s) * NG_ + g) * 49 + j;
        betas[vv * 50 + j] = beta[off];
    }
    __syncthreads();

    for (int t = tid; t < 735; t += 256) {
        int vv = t / 49, i = t - vv * 49;
        const float2* kr = (const float2*)(kss + i * 50);
        const float2* bv = (const float2*)(betas + vv * 50);
        float r0 = 0.f, r1 = 0.f;
        #pragma unroll
        for (int c = 0; c < 24; c++) {
            float2 kk = kr[c], bb = bv[c];
            r0 = fmaf(kk.x, bb.x, r0);
            r1 = fmaf(kk.y, bb.y, r1);
        }
        float r = r0 + r1 + kss[i * 50 + 48] * betas[vv * 50 + 48];
        scr[t] = betas[vv * 50 + i] * r;
    }
    __syncthreads();

    if (tid < 15) {
        float acc = 0.f;
        #pragma unroll
        for (int k = 0; k < 49; k++) acc += scr[tid * 49 + k];
        int v = vt * 15 + tid;
        g_p1[((b * NQ_ + v) * NS_ + s) * NG_ + g] = acc;
    }
}

// ---------------------------------------------------------------------------
// k2: per (b,v,g). R4-exact.
// ---------------------------------------------------------------------------
__global__ __launch_bounds__(NT2_, 2) void k2_main(const float* __restrict__ sup,
                                                   const float* __restrict__ qry,
                                                   const float* __restrict__ beta,
                                                   const float* __restrict__ gamma) {
    extern __shared__ float sm[];
    float* xs   = sm;                     // 294*68
    float* rsq  = xs + ROWS_ * STR_;      // 296
    float* bet  = rsq + 296;              // 245
    float* gam  = bet + 245;              // 245
    float* scr  = gam + 245;              // 245
    float* scrq = scr + 245;              // 245
    float* red  = scrq + 245;             // 16

    int bid = blockIdx.x;
    int g = bid & 3;
    int bv = bid >> 2;
    int b = bv / NQ_;
    int tid = threadIdx.x;

    const float* supb = sup + (size_t)(b * (NS_ * NG_) + g) * 49 * 64;
    const float* qryb = qry + ((size_t)bv * NG_ + g) * 49 * 64;

    for (int idx = tid; idx < ROWS_ * 16; idx += NT2_) {
        int r = idx >> 4, c4 = idx & 15;
        float4 val;
        if (r < 245) {
            int s = r / 49;
            int i = r - s * 49;
            val = *(const float4*)(supb + (size_t)s * (NG_ * 49 * 64) + i * 64 + c4 * 4);
        } else {
            val = *(const float4*)(qryb + (r - 245) * 64 + c4 * 4);
        }
        *(float4*)(xs + r * STR_ + c4 * 4) = val;
    }
    for (int idx = tid; idx < NS_ * 49; idx += NT2_) {
        int s = idx / 49, j = idx - s * 49;
        size_t off = ((size_t)(bv * NS_ + s) * NG_ + g) * 49 + j;
        bet[idx] = beta[off];
        gam[idx] = gamma[off];
    }
    __syncthreads();

    for (int r = tid; r < ROWS_; r += NT2_) {
        const float2* xr = (const float2*)(xs + r * STR_);
        float a0 = 0.f, a1 = 0.f;
        #pragma unroll
        for (int c = 0; c < 32; c++) { float2 x = xr[c]; a0 = fmaf(x.x, x.x, a0); a1 = fmaf(x.y, x.y, a1); }
        rsq[r] = a0 + a1;
    }
    __syncthreads();

    bool active = (tid < ROWS_);
    int it = tid / 7;
    int jt = tid - it * 7;

    if (active) {
        float acc[49];
        #pragma unroll
        for (int k = 0; k < 49; k++) acc[k] = 0.0f;

        const float2* A  = (const float2*)(xs + it * 7 * STR_);
        const float2* Bm = (const float2*)(xs + (245 + jt * 7) * STR_);
        #pragma unroll 1
        for (int c2 = 0; c2 < 32; c2++) {
            float2 a[7], bb[7];
            #pragma unroll
            for (int k = 0; k < 7; k++) a[k]  = A[k * (STR_ / 2) + c2];
            #pragma unroll
            for (int k = 0; k < 7; k++) bb[k] = Bm[k * (STR_ / 2) + c2];
            #pragma unroll
            for (int ii = 0; ii < 7; ii++)
                #pragma unroll
                for (int jj = 0; jj < 7; jj++) {
                    acc[ii * 7 + jj] = fmaf(a[ii].x, bb[jj].x, acc[ii * 7 + jj]);
                    acc[ii * 7 + jj] = fmaf(a[ii].y, bb[jj].y, acc[ii * 7 + jj]);
                }
        }

        float qsq[7];
        int jbase = jt * 7;
        #pragma unroll
        for (int jj = 0; jj < 7; jj++) qsq[jj] = rsq[245 + jbase + jj];
        #pragma unroll
        for (int ii = 0; ii < 7; ii++) {
            float ri = rsq[it * 7 + ii];
            #pragma unroll
            for (int jj = 0; jj < 7; jj++) {
                float d2 = ri + qsq[jj] - 2.0f * acc[ii * 7 + jj];
                acc[ii * 7 + jj] = multi_gauss(d2);
            }
        }

        if (it < 35) {
            int s = it / 7;
            int i0 = it * 7 - s * 49;
            const float* gs = gam + s * 49 + jbase;
            const float* bs = bet + s * 49 + i0;
            float partial = 0.0f;
            #pragma unroll
            for (int ii = 0; ii < 7; ii++) {
                float rowsum = 0.0f;
                #pragma unroll
                for (int jj = 0; jj < 7; jj++) rowsum = fmaf(acc[ii * 7 + jj], gs[jj], rowsum);
                partial = fmaf(bs[ii], rowsum, partial);
            }
            scr[tid] = partial;
        } else {
            int q0 = it * 7 - 245;
            int qt = tid - 245;
            #pragma unroll
            for (int s = 0; s < 5; s++) {
                const float* gs = gam + s * 49;
                float pq = 0.0f;
                #pragma unroll
                for (int ii = 0; ii < 7; ii++) {
                    float rowsum = 0.0f;
                    #pragma unroll
                    for (int jj = 0; jj < 7; jj++) rowsum = fmaf(acc[ii * 7 + jj], gs[jbase + jj], rowsum);
                    pq = fmaf(gs[q0 + ii], rowsum, pq);
                }
                scrq[s * 49 + qt] = pq;
            }
        }
    }
    __syncthreads();

    if (tid < 10) {
        int s = tid % 5;
        const float* src = (tid < 5) ? (scr + s * 49) : (scrq + s * 49);
        float acc2 = 0.f;
        #pragma unroll
        for (int k = 0; k < 49; k++) acc2 += src[k];
        red[tid] = acc2;
    }
    __syncthreads();

    if (tid < NS_) {
        int idx = (bv * NS_ + tid) * NG_ + g;
        g_p2[idx] = red[5 + tid] - 2.0f * red[tid];
    }
}

__global__ void k3_reduce(float* __restrict__ out) {
    int o = blockIdx.x * blockDim.x + threadIdx.x;
    if (o < B_ * NQ_ * NS_) {
        float s = 0.0f;
        #pragma unroll
        for (int g = 0; g < NG_; g++) s += g_p1[o * NG_ + g] + g_p2[o * NG_ + g];
        out[o] = 0.25f * s;
    }
}

extern "C" void kernel_launch(void* const* d_in, const int* in_sizes, int n_in,
                              void* d_out, int out_size) {
    const float* sup   = (const float*)d_in[0];
    const float* qry   = (const float*)d_in[1];
    const float* beta  = (const float*)d_in[2];
    const float* gamma = (const float*)d_in[3];
    float* out = (float*)d_out;

    const int smem2 = (ROWS_ * STR_ + 296 + 245 * 4 + 16) * (int)sizeof(float);
    static bool configured = false;
    if (!configured) {
        cudaFuncSetAttribute(k2_main, cudaFuncAttributeMaxDynamicSharedMemorySize, smem2);
        configured = true;
    }

    k1a_kss<<<B_ * NS_ * NG_, 192>>>(sup);
    k1b_bilinear<<<B_ * NS_ * NG_ * 5, 256>>>(beta);
    k2_main<<<B_ * NQ_ * NG_, NT2_, smem2>>>(sup, qry, beta, gamma);
    k3_reduce<<<(B_ * NQ_ * NS_ + 255) / 256, 256>>>(out);
}

// round 12
// speedup vs baseline: 1.0554x; 1.0201x over previous
#include <cuda_runtime.h>
#include <cstdint>

#define B_   8
#define NQ_  75
#define NS_  5
#define NG_  4
#define NF_  49
#define C_   64

#define ROWS_ 294
#define STR_  68
#define NT2_  320

// scale constants: t = exp(-d2/8) = 2^(-0.1803368801*d2)
#define NEG_L2E8  (-0.18033688011112042f)   // -0.125*log2(e)
#define POS_L2E4  ( 0.36067376022224084f)   //  0.25*log2(e)  (coeff of dot)

__device__ float g_p1[B_ * NQ_ * NS_ * NG_];
__device__ float g_p2[B_ * NQ_ * NS_ * NG_];
__device__ float g_kss[B_ * NS_ * NG_ * NF_ * NF_];

// multi-gauss from precomputed log2-scaled argument:
// arg = -0.1803*d2 ;  returns t+t^2+t^4+t^8+t^16 with t=2^arg
__device__ __forceinline__ float mg_from_arg(float arg) {
    float t;
    asm("ex2.approx.f32 %0, %1;" : "=f"(t) : "f"(arg));
    float t2 = t * t;
    float s1 = fmaf(t, t, t);        // t + t^2
    float t4 = t2 * t2;
    float t8 = t4 * t4;
    float s2 = fmaf(t8, t8, t8);     // t^8 + t^16
    return (s1 + t4) + s2;
}

// ---------------------------------------------------------------------------
// k1a: per (b,s,g) -> Kss (49x49) once -> g_kss.
// 169 threads, 13x13 grid of 4x4 micro-tiles (rows padded to 52).
// ---------------------------------------------------------------------------
__global__ __launch_bounds__(192) void k1a_kss(const float* __restrict__ sup) {
    __shared__ float xs[52 * STR_];
    __shared__ float ssq[52];        // pre-scaled: -0.1803 * sum(x^2)

    int bid = blockIdx.x;            // 0..159 = (b*5+s)*4+g
    int tid = threadIdx.x;

    const float* sb = sup + (size_t)bid * 49 * 64;
    for (int idx = tid; idx < 52 * 16; idx += 192) {
        int r = idx >> 4, c4 = idx & 15;
        float4 v = make_float4(0.f, 0.f, 0.f, 0.f);
        if (r < 49) v = *(const float4*)(sb + r * 64 + c4 * 4);
        *(float4*)(xs + r * STR_ + c4 * 4) = v;
    }
    __syncthreads();

    if (tid < 52) {
        const float2* xr = (const float2*)(xs + tid * STR_);
        float a0 = 0.f, a1 = 0.f;
        #pragma unroll
        for (int c = 0; c < 32; c++) { float2 x = xr[c]; a0 = fmaf(x.x, x.x, a0); a1 = fmaf(x.y, x.y, a1); }
        ssq[tid] = NEG_L2E8 * (a0 + a1);
    }
    __syncthreads();

    if (tid < 169) {
        int it = tid / 13, jt = tid - it * 13;
        float acc[16];
        #pragma unroll
        for (int k = 0; k < 16; k++) acc[k] = 0.f;
        const float2* A  = (const float2*)(xs + it * 4 * STR_);
        const float2* Bm = (const float2*)(xs + jt * 4 * STR_);
        #pragma unroll 2
        for (int c2 = 0; c2 < 32; c2++) {
            float2 a[4], bb[4];
            #pragma unroll
            for (int k = 0; k < 4; k++) a[k]  = A[k * (STR_ / 2) + c2];
            #pragma unroll
            for (int k = 0; k < 4; k++) bb[k] = Bm[k * (STR_ / 2) + c2];
            #pragma unroll
            for (int ii = 0; ii < 4; ii++)
                #pragma unroll
                for (int jj = 0; jj < 4; jj++) {
                    acc[ii * 4 + jj] = fmaf(a[ii].x, bb[jj].x, acc[ii * 4 + jj]);
                    acc[ii * 4 + jj] = fmaf(a[ii].y, bb[jj].y, acc[ii * 4 + jj]);
                }
        }
        float* kout = g_kss + (size_t)bid * 2401;
        #pragma unroll
        for (int ii = 0; ii < 4; ii++) {
            int i = it * 4 + ii;
            if (i < 49) {
                float ai = ssq[i];
                #pragma unroll
                for (int jj = 0; jj < 4; jj++) {
                    int j = jt * 4 + jj;
                    if (j < 49) {
                        float arg = fmaf(POS_L2E4, acc[ii * 4 + jj], ai + ssq[j]);
                        kout[i * 49 + j] = mg_from_arg(arg);
                    }
                }
            }
        }
    }
}

// ---------------------------------------------------------------------------
// k1b: per (b,s,g,vchunk of 15) -> beta^T Kss beta (Kss L2-hot)
// ---------------------------------------------------------------------------
__global__ __launch_bounds__(256) void k1b_bilinear(const float* __restrict__ beta) {
    __shared__ float kss[49 * 50];
    __shared__ float betas[15 * 50];
    __shared__ float scr[735];

    int bid = blockIdx.x;
    int g = bid & 3;
    int rest = bid >> 2;
    int s = rest % NS_;  rest /= NS_;
    int vt = rest % 5;
    int b = rest / 5;
    int tid = threadIdx.x;

    int bid160 = (b * NS_ + s) * NG_ + g;
    const float* ksrc = g_kss + (size_t)bid160 * 2401;
    for (int idx = tid; idx < 2401; idx += 256) {
        int i = idx / 49, j = idx - i * 49;
        kss[i * 50 + j] = ksrc[idx];
    }
    for (int idx = tid; idx < 15 * 49; idx += 256) {
        int vv = idx / 49, j = idx - vv * 49;
        int v = vt * 15 + vv;
        size_t off = ((size_t)((b * NQ_ + v) * NS_ + s) * NG_ + g) * 49 + j;
        betas[vv * 50 + j] = beta[off];
    }
    __syncthreads();

    for (int t = tid; t < 735; t += 256) {
        int vv = t / 49, i = t - vv * 49;
        const float2* kr = (const float2*)(kss + i * 50);
        const float2* bv = (const float2*)(betas + vv * 50);
        float r0 = 0.f, r1 = 0.f;
        #pragma unroll
        for (int c = 0; c < 24; c++) {
            float2 kk = kr[c], bb = bv[c];
            r0 = fmaf(kk.x, bb.x, r0);
            r1 = fmaf(kk.y, bb.y, r1);
        }
        float r = r0 + r1 + kss[i * 50 + 48] * betas[vv * 50 + 48];
        scr[t] = betas[vv * 50 + i] * r;
    }
    __syncthreads();

    if (tid < 15) {
        float acc = 0.f;
        #pragma unroll
        for (int k = 0; k < 49; k++) acc += scr[tid * 49 + k];
        int v = vt * 15 + tid;
        g_p1[((b * NQ_ + v) * NS_ + s) * NG_ + g] = acc;
    }
}

// ---------------------------------------------------------------------------
// k2: per (b,v,g). R4 structure; epilogue with folded log2-scaled exp arg:
//   arg = 0.3607*dot + (a_i + a_j),  a_r = -0.1803*sum(x_r^2)
// (clamp dropped: d2<0 only by ~1e-5 rounding -> kernel value err ~1e-6 rel)
// ---------------------------------------------------------------------------
__global__ __launch_bounds__(NT2_, 2) void k2_main(const float* __restrict__ sup,
                                                   const float* __restrict__ qry,
                                                   const float* __restrict__ beta,
                                                   const float* __restrict__ gamma) {
    extern __shared__ float sm[];
    float* xs   = sm;                     // 294*68
    float* rsq  = xs + ROWS_ * STR_;      // 296 (pre-scaled)
    float* bet  = rsq + 296;              // 245
    float* gam  = bet + 245;              // 245
    float* scr  = gam + 245;              // 245
    float* scrq = scr + 245;              // 245
    float* red  = scrq + 245;             // 16

    int bid = blockIdx.x;
    int g = bid & 3;
    int bv = bid >> 2;
    int b = bv / NQ_;
    int tid = threadIdx.x;

    const float* supb = sup + (size_t)(b * (NS_ * NG_) + g) * 49 * 64;
    const float* qryb = qry + ((size_t)bv * NG_ + g) * 49 * 64;

    for (int idx = tid; idx < ROWS_ * 16; idx += NT2_) {
        int r = idx >> 4, c4 = idx & 15;
        float4 val;
        if (r < 245) {
            int s = r / 49;
            int i = r - s * 49;
            val = *(const float4*)(supb + (size_t)s * (NG_ * 49 * 64) + i * 64 + c4 * 4);
        } else {
            val = *(const float4*)(qryb + (r - 245) * 64 + c4 * 4);
        }
        *(float4*)(xs + r * STR_ + c4 * 4) = val;
    }
    for (int idx = tid; idx < NS_ * 49; idx += NT2_) {
        int s = idx / 49, j = idx - s * 49;
        size_t off = ((size_t)(bv * NS_ + s) * NG_ + g) * 49 + j;
        bet[idx] = beta[off];
        gam[idx] = gamma[off];
    }
    __syncthreads();

    for (int r = tid; r < ROWS_; r += NT2_) {
        const float2* xr = (const float2*)(xs + r * STR_);
        float a0 = 0.f, a1 = 0.f;
        #pragma unroll
        for (int c = 0; c < 32; c++) { float2 x = xr[c]; a0 = fmaf(x.x, x.x, a0); a1 = fmaf(x.y, x.y, a1); }
        rsq[r] = NEG_L2E8 * (a0 + a1);
    }
    __syncthreads();

    bool active = (tid < ROWS_);
    int it = tid / 7;
    int jt = tid - it * 7;

    if (active) {
        float acc[49];
        #pragma unroll
        for (int k = 0; k < 49; k++) acc[k] = 0.0f;

        const float2* A  = (const float2*)(xs + it * 7 * STR_);
        const float2* Bm = (const float2*)(xs + (245 + jt * 7) * STR_);
        #pragma unroll 1
        for (int c2 = 0; c2 < 32; c2++) {
            float2 a[7], bb[7];
            #pragma unroll
            for (int k = 0; k < 7; k++) a[k]  = A[k * (STR_ / 2) + c2];
            #pragma unroll
            for (int k = 0; k < 7; k++) bb[k] = Bm[k * (STR_ / 2) + c2];
            #pragma unroll
            for (int ii = 0; ii < 7; ii++)
                #pragma unroll
                for (int jj = 0; jj < 7; jj++) {
                    acc[ii * 7 + jj] = fmaf(a[ii].x, bb[jj].x, acc[ii * 7 + jj]);
                    acc[ii * 7 + jj] = fmaf(a[ii].y, bb[jj].y, acc[ii * 7 + jj]);
                }
        }

        float qsq[7];
        int jbase = jt * 7;
        #pragma unroll
        for (int jj = 0; jj < 7; jj++) qsq[jj] = rsq[245 + jbase + jj];
        #pragma unroll
        for (int ii = 0; ii < 7; ii++) {
            float ai = rsq[it * 7 + ii];
            #pragma unroll
            for (int jj = 0; jj < 7; jj++) {
                float arg = fmaf(POS_L2E4, acc[ii * 7 + jj], ai + qsq[jj]);
                acc[ii * 7 + jj] = mg_from_arg(arg);
            }
        }

        if (it < 35) {
            int s = it / 7;
            int i0 = it * 7 - s * 49;
            const float* gs = gam + s * 49 + jbase;
            const float* bs = bet + s * 49 + i0;
            float partial = 0.0f;
            #pragma unroll
            for (int ii = 0; ii < 7; ii++) {
                float rowsum = 0.0f;
                #pragma unroll
                for (int jj = 0; jj < 7; jj++) rowsum = fmaf(acc[ii * 7 + jj], gs[jj], rowsum);
                partial = fmaf(bs[ii], rowsum, partial);
            }
            scr[tid] = partial;
        } else {
            int q0 = it * 7 - 245;
            int qt = tid - 245;
            #pragma unroll
            for (int s = 0; s < 5; s++) {
                const float* gs = gam + s * 49;
                float pq = 0.0f;
                #pragma unroll
                for (int ii = 0; ii < 7; ii++) {
                    float rowsum = 0.0f;
                    #pragma unroll
                    for (int jj = 0; jj < 7; jj++) rowsum = fmaf(acc[ii * 7 + jj], gs[jbase + jj], rowsum);
                    pq = fmaf(gs[q0 + ii], rowsum, pq);
                }
                scrq[s * 49 + qt] = pq;
            }
        }
    }
    __syncthreads();

    if (tid < 10) {
        int s = tid % 5;
        const float* src = (tid < 5) ? (scr + s * 49) : (scrq + s * 49);
        float acc2 = 0.f;
        #pragma unroll
        for (int k = 0; k < 49; k++) acc2 += src[k];
        red[tid] = acc2;
    }
    __syncthreads();

    if (tid < NS_) {
        int idx = (bv * NS_ + tid) * NG_ + g;
        g_p2[idx] = red[5 + tid] - 2.0f * red[tid];
    }
}

__global__ void k3_reduce(float* __restrict__ out) {
    int o = blockIdx.x * blockDim.x + threadIdx.x;
    if (o < B_ * NQ_ * NS_) {
        float s = 0.0f;
        #pragma unroll
        for (int g = 0; g < NG_; g++) s += g_p1[o * NG_ + g] + g_p2[o * NG_ + g];
        out[o] = 0.25f * s;
    }
}

extern "C" void kernel_launch(void* const* d_in, const int* in_sizes, int n_in,
                              void* d_out, int out_size) {
    const float* sup   = (const float*)d_in[0];
    const float* qry   = (const float*)d_in[1];
    const float* beta  = (const float*)d_in[2];
    const float* gamma = (const float*)d_in[3];
    float* out = (float*)d_out;

    const int smem2 = (ROWS_ * STR_ + 296 + 245 * 4 + 16) * (int)sizeof(float);
    static bool configured = false;
    if (!configured) {
        cudaFuncSetAttribute(k2_main, cudaFuncAttributeMaxDynamicSharedMemorySize, smem2);
        configured = true;
    }

    k1a_kss<<<B_ * NS_ * NG_, 192>>>(sup);
    k1b_bilinear<<<B_ * NS_ * NG_ * 5, 256>>>(beta);
    k2_main<<<B_ * NQ_ * NG_, NT2_, smem2>>>(sup, qry, beta, gamma);
    k3_reduce<<<(B_ * NQ_ * NS_ + 255) / 256, 256>>>(out);
}